// round 6
// baseline (speedup 1.0000x reference)
#include <cuda_runtime.h>
#include <cuda_bf16.h>

// out[b,i,o] = relu( sum_f s[b,i,f] * W[f,o] + bias[o] * deg[b,i] )
// where s[b,i,f] = sum_j adj[b,i,j] * concat(sf1,sf2)[b,i,j,f]
//       deg[b,i] = sum_j adj[b,i,j]
//
// Round 6: 512 threads, 4 rows/block (grid 512), FOUR warps per row.
// Each warp owns a 32-wide j-quarter: single-ballot compaction, list
// zero-padded to a multiple of 8 so the gather loop is always full
// 8-deep batches (no serialized tail). 8192 total warps (4x round 5).

#define RPB   4       // rows per block
#define WPR   4       // warps per row
#define NW    16      // warps per block
#define MJ    128     // neighbor count (j)
#define FE    64      // features per input tensor
#define FC    128     // concatenated features
#define FO    128     // output features

__global__ __launch_bounds__(512, 2)
void gcn_fused_kernel(const float* __restrict__ sf1,
                      const float* __restrict__ sf2,
                      const float* __restrict__ adj,
                      const float* __restrict__ W,
                      const float* __restrict__ bias,
                      float* __restrict__ out)
{
    __shared__ int    s_off[NW][40];         // compacted j*FE offsets (+8 pad)
    __shared__ float  s_val[NW][40];         // compacted adjacency values
    __shared__ float  s_part[NW][FC];        // per-warp partial s vectors
    __shared__ float  s_sm[RPB][FC];         // per-row aggregated features
    __shared__ float  s_degp[NW];
    __shared__ float  s_deg[RPB];
    __shared__ float4 red4[NW][RPB][32];     // GEMM partials

    const int row0 = blockIdx.x * RPB;
    const int t    = threadIdx.x;
    const int w    = t >> 5;
    const int lane = t & 31;
    const int pr   = w >> 2;                 // row within block
    const int q    = w & 3;                  // j-quarter
    const int row  = row0 + pr;

    // ---- Phase 1 (warp-local): 32 adj values, single-ballot compaction ----
    const int   j = q * 32 + lane;
    const float a = __ldg(adj + (size_t)row * MJ + j);
    const unsigned bal = __ballot_sync(0xffffffffu, a != 0.0f);
    const int nnz = __popc(bal);
    if (a != 0.0f) {
        const int p = __popc(bal & ((1u << lane) - 1u));
        s_off[w][p] = j * FE;
        s_val[w][p] = a;
    }
    if (lane < 8) {                          // zero-pad to full 8-batch
        s_off[w][nnz + lane] = 0;
        s_val[w][nnz + lane] = 0.0f;
    }
    {
        float d = a;
        #pragma unroll
        for (int off = 16; off > 0; off >>= 1)
            d += __shfl_down_sync(0xffffffffu, d, off);
        if (lane == 0) s_degp[w] = d;
    }
    __syncwarp();

    // ---- Phase 2 (warp-local): gather, always full 8-deep batches ----
    // lanes 0-15: sf1 (channels 0..63); lanes 16-31: sf2 (channels 64..127).
    {
        const float* base = ((lane < 16) ? sf1 : sf2)
                          + (size_t)row * MJ * FE + (lane & 15) * 4;
        float4 acc0 = make_float4(0.f, 0.f, 0.f, 0.f);
        float4 acc1 = make_float4(0.f, 0.f, 0.f, 0.f);
        for (int k = 0; k < nnz; k += 8) {   // padded: batch always valid
            const int o0 = s_off[w][k    ], o1 = s_off[w][k + 1];
            const int o2 = s_off[w][k + 2], o3 = s_off[w][k + 3];
            const int o4 = s_off[w][k + 4], o5 = s_off[w][k + 5];
            const int o6 = s_off[w][k + 6], o7 = s_off[w][k + 7];
            const float4 v0 = __ldcs(reinterpret_cast<const float4*>(base + o0));
            const float4 v1 = __ldcs(reinterpret_cast<const float4*>(base + o1));
            const float4 v2 = __ldcs(reinterpret_cast<const float4*>(base + o2));
            const float4 v3 = __ldcs(reinterpret_cast<const float4*>(base + o3));
            const float4 v4 = __ldcs(reinterpret_cast<const float4*>(base + o4));
            const float4 v5 = __ldcs(reinterpret_cast<const float4*>(base + o5));
            const float4 v6 = __ldcs(reinterpret_cast<const float4*>(base + o6));
            const float4 v7 = __ldcs(reinterpret_cast<const float4*>(base + o7));
            const float q0 = s_val[w][k    ], q1 = s_val[w][k + 1];
            const float q2 = s_val[w][k + 2], q3 = s_val[w][k + 3];
            const float q4 = s_val[w][k + 4], q5 = s_val[w][k + 5];
            const float q6 = s_val[w][k + 6], q7 = s_val[w][k + 7];
            acc0.x += q0 * v0.x; acc0.y += q0 * v0.y; acc0.z += q0 * v0.z; acc0.w += q0 * v0.w;
            acc1.x += q1 * v1.x; acc1.y += q1 * v1.y; acc1.z += q1 * v1.z; acc1.w += q1 * v1.w;
            acc0.x += q2 * v2.x; acc0.y += q2 * v2.y; acc0.z += q2 * v2.z; acc0.w += q2 * v2.w;
            acc1.x += q3 * v3.x; acc1.y += q3 * v3.y; acc1.z += q3 * v3.z; acc1.w += q3 * v3.w;
            acc0.x += q4 * v4.x; acc0.y += q4 * v4.y; acc0.z += q4 * v4.z; acc0.w += q4 * v4.w;
            acc1.x += q5 * v5.x; acc1.y += q5 * v5.y; acc1.z += q5 * v5.z; acc1.w += q5 * v5.w;
            acc0.x += q6 * v6.x; acc0.y += q6 * v6.y; acc0.z += q6 * v6.z; acc0.w += q6 * v6.w;
            acc1.x += q7 * v7.x; acc1.y += q7 * v7.y; acc1.z += q7 * v7.z; acc1.w += q7 * v7.w;
        }
        float4 s4;
        s4.x = acc0.x + acc1.x; s4.y = acc0.y + acc1.y;
        s4.z = acc0.z + acc1.z; s4.w = acc0.w + acc1.w;
        reinterpret_cast<float4*>(s_part[w])[lane] = s4;
    }
    __syncthreads();

    // ---- Phase 3a: combine 4 quarter-partials per (row, channel) ----
    {
        const int r = t >> 7;                // 512 threads = 4 rows x 128 ch
        const int c = t & 127;
        s_sm[r][c] = (s_part[r * 4 + 0][c] + s_part[r * 4 + 1][c])
                   + (s_part[r * 4 + 2][c] + s_part[r * 4 + 3][c]);
        if (t < RPB)
            s_deg[t] = (s_degp[t * 4 + 0] + s_degp[t * 4 + 1])
                     + (s_degp[t * 4 + 2] + s_degp[t * 4 + 3]);
    }
    __syncthreads();

    // ---- Phase 3b: GEMM, split-K 16 ways, 4-row register blocking ----
    {
        const int f0 = w * 8;
        const float4* W4 = reinterpret_cast<const float4*>(W);
        float4 a0 = make_float4(0.f, 0.f, 0.f, 0.f);
        float4 a1 = make_float4(0.f, 0.f, 0.f, 0.f);
        float4 a2 = make_float4(0.f, 0.f, 0.f, 0.f);
        float4 a3 = make_float4(0.f, 0.f, 0.f, 0.f);
        #pragma unroll
        for (int kk = 0; kk < 8; ++kk) {
            const int f = f0 + kk;
            const float4 wv = W4[f * 32 + lane];   // L1/L2-resident
            const float s0 = s_sm[0][f];
            const float s1 = s_sm[1][f];
            const float s2 = s_sm[2][f];
            const float s3 = s_sm[3][f];
            a0.x += s0 * wv.x; a0.y += s0 * wv.y; a0.z += s0 * wv.z; a0.w += s0 * wv.w;
            a1.x += s1 * wv.x; a1.y += s1 * wv.y; a1.z += s1 * wv.z; a1.w += s1 * wv.w;
            a2.x += s2 * wv.x; a2.y += s2 * wv.y; a2.z += s2 * wv.z; a2.w += s2 * wv.w;
            a3.x += s3 * wv.x; a3.y += s3 * wv.y; a3.z += s3 * wv.z; a3.w += s3 * wv.w;
        }
        red4[w][0][lane] = a0;
        red4[w][1][lane] = a1;
        red4[w][2][lane] = a2;
        red4[w][3][lane] = a3;
    }
    __syncthreads();

    // ---- Phase 4: combine 16 f-slices + bias*deg + relu + store ----
    if (t < RPB * 32) {
        const int r  = t >> 5;
        const int oq = t & 31;
        float4 rs = red4[0][r][oq];
        #pragma unroll
        for (int sl = 1; sl < NW; ++sl) {
            const float4 p = red4[sl][r][oq];
            rs.x += p.x; rs.y += p.y; rs.z += p.z; rs.w += p.w;
        }
        const float4 bb = reinterpret_cast<const float4*>(bias)[oq];
        const float  d  = s_deg[r];
        float4 o4;
        o4.x = fmaxf(rs.x + bb.x * d, 0.0f);
        o4.y = fmaxf(rs.y + bb.y * d, 0.0f);
        o4.z = fmaxf(rs.z + bb.z * d, 0.0f);
        o4.w = fmaxf(rs.w + bb.w * d, 0.0f);
        reinterpret_cast<float4*>(out)[(size_t)(row0 + r) * 32 + oq] = o4;
    }
}

extern "C" void kernel_launch(void* const* d_in, const int* in_sizes, int n_in,
                              void* d_out, int out_size)
{
    const float* sf1  = (const float*)d_in[0];  // (16,128,128,64)
    const float* sf2  = (const float*)d_in[1];  // (16,128,128,64)
    const float* adj  = (const float*)d_in[2];  // (16,128,128)
    const float* W    = (const float*)d_in[3];  // (128,128)
    const float* bias = (const float*)d_in[4];  // (128,)
    float* out = (float*)d_out;                 // (16,128,128)

    gcn_fused_kernel<<<2048 / RPB, 512>>>(sf1, sf2, adj, W, bias, out);
}

// round 7
// speedup vs baseline: 1.1752x; 1.1752x over previous
#include <cuda_runtime.h>
#include <cuda_bf16.h>

// out[b,i,o] = relu( sum_f s[b,i,f] * W[f,o] + bias[o] * deg[b,i] )
// where s[b,i,f] = sum_j adj[b,i,j] * concat(sf1,sf2)[b,i,j,f]
//       deg[b,i] = sum_j adj[b,i,j]
//
// Round 7: TWO warps per row. 256 threads = 8 warps = 4 rows/block,
// grid 1024 -> 4096 total warps (2x round 5's cap). Each warp owns a
// 64-wide j-half: ~16 compacted entries = 2 full 8-deep load batches
// (zero-padded, no tail). Cheap 2-way combine, 4-row-blocked GEMM.

#define RPB   4       // rows per block
#define NW    8       // warps per block
#define MJ    128     // neighbor count (j)
#define FE    64      // features per input tensor
#define FC    128     // concatenated features
#define FO    128     // output features

__global__ __launch_bounds__(256, 4)
void gcn_fused_kernel(const float* __restrict__ sf1,
                      const float* __restrict__ sf2,
                      const float* __restrict__ adj,
                      const float* __restrict__ W,
                      const float* __restrict__ bias,
                      float* __restrict__ out)
{
    __shared__ int    s_off[NW][72];         // compacted j*FE offsets (+pad)
    __shared__ float  s_val[NW][72];         // compacted adjacency values
    __shared__ float  s_part[NW][FC];        // per-warp partial s vectors
    __shared__ float  s_sm[RPB][FC];         // per-row aggregated features
    __shared__ float  s_degp[NW];
    __shared__ float  s_deg[RPB];
    __shared__ float4 red4[NW][RPB][32];     // GEMM partials

    const int row0 = blockIdx.x * RPB;
    const int t    = threadIdx.x;
    const int w    = t >> 5;
    const int lane = t & 31;
    const int pr   = w >> 1;                 // row within block
    const int h    = w & 1;                  // j-half (0: j<64, 1: j>=64)
    const int row  = row0 + pr;

    // ---- Phase 1 (warp-local): 64 adj values, 2-segment compaction ----
    const float* arow = adj + (size_t)row * MJ + h * 64;
    const float a0 = __ldg(arow + lane);
    const float a1 = __ldg(arow + lane + 32);

    const unsigned b0 = __ballot_sync(0xffffffffu, a0 != 0.0f);
    const unsigned b1 = __ballot_sync(0xffffffffu, a1 != 0.0f);
    const int c0  = __popc(b0);
    const int nnz = c0 + __popc(b1);

    const unsigned lm = (1u << lane) - 1u;
    if (a0 != 0.0f) { const int p = __popc(b0 & lm);
                      s_off[w][p] = (h * 64 + lane     ) * FE; s_val[w][p] = a0; }
    if (a1 != 0.0f) { const int p = c0 + __popc(b1 & lm);
                      s_off[w][p] = (h * 64 + lane + 32) * FE; s_val[w][p] = a1; }
    if (lane < 8) {                          // zero-pad: batches always full
        s_off[w][nnz + lane] = 0;
        s_val[w][nnz + lane] = 0.0f;
    }
    {
        float d = a0 + a1;
        #pragma unroll
        for (int off = 16; off > 0; off >>= 1)
            d += __shfl_down_sync(0xffffffffu, d, off);
        if (lane == 0) s_degp[w] = d;
    }
    __syncwarp();

    // ---- Phase 2 (warp-local): gather, full 8-deep batches ----
    // lanes 0-15: sf1 (channels 0..63); lanes 16-31: sf2 (channels 64..127).
    {
        const float* base = ((lane < 16) ? sf1 : sf2)
                          + (size_t)row * MJ * FE + (lane & 15) * 4;
        float4 acc0 = make_float4(0.f, 0.f, 0.f, 0.f);
        float4 acc1 = make_float4(0.f, 0.f, 0.f, 0.f);
        for (int k = 0; k < nnz; k += 8) {   // padded: batch always valid
            const int o0 = s_off[w][k    ], o1 = s_off[w][k + 1];
            const int o2 = s_off[w][k + 2], o3 = s_off[w][k + 3];
            const int o4 = s_off[w][k + 4], o5 = s_off[w][k + 5];
            const int o6 = s_off[w][k + 6], o7 = s_off[w][k + 7];
            const float4 v0 = __ldcs(reinterpret_cast<const float4*>(base + o0));
            const float4 v1 = __ldcs(reinterpret_cast<const float4*>(base + o1));
            const float4 v2 = __ldcs(reinterpret_cast<const float4*>(base + o2));
            const float4 v3 = __ldcs(reinterpret_cast<const float4*>(base + o3));
            const float4 v4 = __ldcs(reinterpret_cast<const float4*>(base + o4));
            const float4 v5 = __ldcs(reinterpret_cast<const float4*>(base + o5));
            const float4 v6 = __ldcs(reinterpret_cast<const float4*>(base + o6));
            const float4 v7 = __ldcs(reinterpret_cast<const float4*>(base + o7));
            const float q0 = s_val[w][k    ], q1 = s_val[w][k + 1];
            const float q2 = s_val[w][k + 2], q3 = s_val[w][k + 3];
            const float q4 = s_val[w][k + 4], q5 = s_val[w][k + 5];
            const float q6 = s_val[w][k + 6], q7 = s_val[w][k + 7];
            acc0.x += q0 * v0.x; acc0.y += q0 * v0.y; acc0.z += q0 * v0.z; acc0.w += q0 * v0.w;
            acc1.x += q1 * v1.x; acc1.y += q1 * v1.y; acc1.z += q1 * v1.z; acc1.w += q1 * v1.w;
            acc0.x += q2 * v2.x; acc0.y += q2 * v2.y; acc0.z += q2 * v2.z; acc0.w += q2 * v2.w;
            acc1.x += q3 * v3.x; acc1.y += q3 * v3.y; acc1.z += q3 * v3.z; acc1.w += q3 * v3.w;
            acc0.x += q4 * v4.x; acc0.y += q4 * v4.y; acc0.z += q4 * v4.z; acc0.w += q4 * v4.w;
            acc1.x += q5 * v5.x; acc1.y += q5 * v5.y; acc1.z += q5 * v5.z; acc1.w += q5 * v5.w;
            acc0.x += q6 * v6.x; acc0.y += q6 * v6.y; acc0.z += q6 * v6.z; acc0.w += q6 * v6.w;
            acc1.x += q7 * v7.x; acc1.y += q7 * v7.y; acc1.z += q7 * v7.z; acc1.w += q7 * v7.w;
        }
        float4 s4;
        s4.x = acc0.x + acc1.x; s4.y = acc0.y + acc1.y;
        s4.z = acc0.z + acc1.z; s4.w = acc0.w + acc1.w;
        reinterpret_cast<float4*>(s_part[w])[lane] = s4;
    }
    __syncthreads();

    // ---- Phase 3a: combine 2 half-partials per (row, channel) ----
    {
        #pragma unroll
        for (int idx = t; idx < RPB * FC; idx += 256) {
            const int r = idx >> 7;
            const int c = idx & 127;
            s_sm[r][c] = s_part[r * 2 + 0][c] + s_part[r * 2 + 1][c];
        }
        if (t < RPB) s_deg[t] = s_degp[t * 2] + s_degp[t * 2 + 1];
    }
    __syncthreads();

    // ---- Phase 3b: GEMM, split-K 8 ways, 4-row register blocking ----
    {
        const int f0 = w * 16;
        const float4* W4 = reinterpret_cast<const float4*>(W);
        float4 a0r = make_float4(0.f, 0.f, 0.f, 0.f);
        float4 a1r = make_float4(0.f, 0.f, 0.f, 0.f);
        float4 a2r = make_float4(0.f, 0.f, 0.f, 0.f);
        float4 a3r = make_float4(0.f, 0.f, 0.f, 0.f);
        #pragma unroll
        for (int kk = 0; kk < 16; ++kk) {
            const int f = f0 + kk;
            const float4 wv = W4[f * 32 + lane];   // L1/L2-resident
            const float s0 = s_sm[0][f];
            const float s1 = s_sm[1][f];
            const float s2 = s_sm[2][f];
            const float s3 = s_sm[3][f];
            a0r.x += s0 * wv.x; a0r.y += s0 * wv.y; a0r.z += s0 * wv.z; a0r.w += s0 * wv.w;
            a1r.x += s1 * wv.x; a1r.y += s1 * wv.y; a1r.z += s1 * wv.z; a1r.w += s1 * wv.w;
            a2r.x += s2 * wv.x; a2r.y += s2 * wv.y; a2r.z += s2 * wv.z; a2r.w += s2 * wv.w;
            a3r.x += s3 * wv.x; a3r.y += s3 * wv.y; a3r.z += s3 * wv.z; a3r.w += s3 * wv.w;
        }
        red4[w][0][lane] = a0r;
        red4[w][1][lane] = a1r;
        red4[w][2][lane] = a2r;
        red4[w][3][lane] = a3r;
    }
    __syncthreads();

    // ---- Phase 4: combine 8 f-slices + bias*deg + relu + store ----
    if (t < RPB * 32) {
        const int r  = t >> 5;
        const int oq = t & 31;
        float4 rs = red4[0][r][oq];
        #pragma unroll
        for (int sl = 1; sl < NW; ++sl) {
            const float4 p = red4[sl][r][oq];
            rs.x += p.x; rs.y += p.y; rs.z += p.z; rs.w += p.w;
        }
        const float4 bb = reinterpret_cast<const float4*>(bias)[oq];
        const float  d  = s_deg[r];
        float4 o4;
        o4.x = fmaxf(rs.x + bb.x * d, 0.0f);
        o4.y = fmaxf(rs.y + bb.y * d, 0.0f);
        o4.z = fmaxf(rs.z + bb.z * d, 0.0f);
        o4.w = fmaxf(rs.w + bb.w * d, 0.0f);
        reinterpret_cast<float4*>(out)[(size_t)(row0 + r) * 32 + oq] = o4;
    }
}

extern "C" void kernel_launch(void* const* d_in, const int* in_sizes, int n_in,
                              void* d_out, int out_size)
{
    const float* sf1  = (const float*)d_in[0];  // (16,128,128,64)
    const float* sf2  = (const float*)d_in[1];  // (16,128,128,64)
    const float* adj  = (const float*)d_in[2];  // (16,128,128)
    const float* W    = (const float*)d_in[3];  // (128,128)
    const float* bias = (const float*)d_in[4];  // (128,)
    float* out = (float*)d_out;                 // (16,128,128)

    gcn_fused_kernel<<<2048 / RPB, 256>>>(sf1, sf2, adj, W, bias, out);
}